// round 10
// baseline (speedup 1.0000x reference)
#include <cuda_runtime.h>
#include <cuda_fp16.h>

#define N_NODES 100000
#define N_EDGES 20000
#define NNZ_E   1600000
#define D       128
#define NT      (N_NODES + N_EDGES)      // combined count array size
#define SCAN_BE 4096                     // elements per scan block
#define SCAN_NB ((NT + SCAN_BE - 1) / SCAN_BE)   // 30
#define CVT_N   (N_NODES * D / 4)        // uint2-granule count for X->fp16

// ---------------- scratch (static device arrays; no cudaMalloc) --------------
__device__ __align__(16) int   g_cnt[NT];
__device__ __align__(16) int   g_excl[NT];
__device__ int   g_bsum[32];
__device__ int   g_rowptr_v[N_NODES + 1];
__device__ int   g_rowptr_e[N_EDGES + 1];
__device__ __align__(16) int g_rank[NNZ_E];   // packed: rank_v | rank_e<<16
__device__ int   g_csr_v[NNZ_E];    // per-vertex list of incident edges
__device__ int   g_csr_e[NNZ_E];    // per-edge list of incident vertices
__device__ float g_inv_sqrt_dv[N_NODES];
__device__ float g_inv_de[N_EDGES];
__device__ float g_se[N_EDGES];     // s_e = sum of inv_sqrt_dv over edge
__device__ __align__(16) float  g_agg[N_EDGES * D];
__device__ __align__(16) __half g_xh[(size_t)N_NODES * D];   // fp16-staged X
__device__ __align__(16) __half g_yeh[(size_t)N_EDGES * D];  // fp16-staged Ye

// ---------------- degree count + rank recording + fused X->fp16 staging -------
// The atomics are latency-bound with idle issue slots; the streaming fp16
// conversion rides along in the same threads for free.
__global__ void k_count(const int* __restrict__ v_idx, const int* __restrict__ e_idx,
                        const float* __restrict__ X) {
    int t = blockIdx.x * blockDim.x + threadIdx.x;
    int i = t * 4;
    if (i < NNZ_E) {                               // NNZ_E % 4 == 0
        int4 v = __ldg((const int4*)(v_idx + i));
        int4 e = __ldg((const int4*)(e_idx + i));
        int rv0 = atomicAdd(&g_cnt[v.x], 1);
        int rv1 = atomicAdd(&g_cnt[v.y], 1);
        int rv2 = atomicAdd(&g_cnt[v.z], 1);
        int rv3 = atomicAdd(&g_cnt[v.w], 1);
        int re0 = atomicAdd(&g_cnt[N_NODES + e.x], 1);
        int re1 = atomicAdd(&g_cnt[N_NODES + e.y], 1);
        int re2 = atomicAdd(&g_cnt[N_NODES + e.z], 1);
        int re3 = atomicAdd(&g_cnt[N_NODES + e.w], 1);
        int4 r;
        r.x = rv0 | (re0 << 16);
        r.y = rv1 | (re1 << 16);
        r.z = rv2 | (re2 << 16);
        r.w = rv3 | (re3 << 16);
        *(int4*)(g_rank + i) = r;
    }
    // fused conversion: 8 float4 granules per thread, independent of atomics
    #pragma unroll
    for (int u = 0; u < 8; u++) {
        int c = t * 8 + u;
        if (c < CVT_N) {
            float4 x = __ldg((const float4*)X + c);
            __half2 h0 = __floats2half2_rn(x.x, x.y);
            __half2 h1 = __floats2half2_rn(x.z, x.w);
            uint2 p = make_uint2(*reinterpret_cast<unsigned*>(&h0),
                                 *reinterpret_cast<unsigned*>(&h1));
            ((uint2*)g_xh)[c] = p;
        }
    }
}

// ---------------- scan phase 1: per-block exclusive + block sums ---------------
__global__ void k_scan1() {
    __shared__ int wsum[32];
    const int tid = threadIdx.x, lane = tid & 31, wid = tid >> 5;
    const int base = blockIdx.x * SCAN_BE + tid * 4;

    int4 x = make_int4(0, 0, 0, 0);
    if (base < NT) x = *(const int4*)(g_cnt + base);   // NT % 4 == 0 -> all-or-none
    int s = x.x + x.y + x.z + x.w;

    int v = s;
    #pragma unroll
    for (int o = 1; o < 32; o <<= 1) {
        int t = __shfl_up_sync(0xffffffffu, v, o);
        if (lane >= o) v += t;
    }
    if (lane == 31) wsum[wid] = v;
    __syncthreads();
    if (wid == 0) {
        int w = wsum[lane];
        #pragma unroll
        for (int o = 1; o < 32; o <<= 1) {
            int t = __shfl_up_sync(0xffffffffu, w, o);
            if (lane >= o) w += t;
        }
        wsum[lane] = w;
    }
    __syncthreads();

    int excl = v - s + (wid ? wsum[wid - 1] : 0);
    if (base < NT) {
        int4 e;
        e.x = excl;
        e.y = e.x + x.x;
        e.z = e.y + x.y;
        e.w = e.z + x.z;
        *(int4*)(g_excl + base) = e;
    }
    if (tid == 0) g_bsum[blockIdx.x] = wsum[31];
}

// ---------------- scan phase 2 (fused): add offsets, emit metadata -------------
__global__ void k_scan3() {
    __shared__ int boff[SCAN_NB];
    const int tid = threadIdx.x;
    if (tid < 32) {                          // warp 0 scans the 30 block sums
        int x = (tid < SCAN_NB) ? g_bsum[tid] : 0;
        int v = x;
        #pragma unroll
        for (int o = 1; o < 32; o <<= 1) {
            int t = __shfl_up_sync(0xffffffffu, v, o);
            if (tid >= o) v += t;
        }
        if (tid < SCAN_NB) boff[tid] = v - x;   // exclusive
    }
    __syncthreads();

    int i = blockIdx.x * blockDim.x + tid;
    if (i >= NT) return;
    int excl = g_excl[i] + boff[i / SCAN_BE];
    int x    = g_cnt[i];
    if (i < N_NODES) {
        g_rowptr_v[i] = excl;
        g_inv_sqrt_dv[i] = (x > 0) ? rsqrtf((float)x) : 0.0f;
        if (i == 0) {
            g_rowptr_v[N_NODES] = NNZ_E;
            g_rowptr_e[N_EDGES] = NNZ_E;
        }
    } else {
        int e  = i - N_NODES;
        g_rowptr_e[e] = excl - NNZ_E;        // edge region starts after all v counts
        g_inv_de[e]   = (x > 0) ? (1.0f / (float)x) : 0.0f;
    }
}

// ---------------- CSR fill: atomic-free via recorded ranks ---------------------
__global__ void k_scatter(const int* __restrict__ v_idx, const int* __restrict__ e_idx) {
    int t = blockIdx.x * blockDim.x + threadIdx.x;
    int i = t * 4;
    if (i < NNZ_E) {
        int4 v = __ldg((const int4*)(v_idx + i));
        int4 e = __ldg((const int4*)(e_idx + i));
        int4 r = *(const int4*)(g_rank + i);
        g_csr_v[__ldg(g_rowptr_v + v.x) + (r.x & 0xffff)] = e.x;
        g_csr_v[__ldg(g_rowptr_v + v.y) + (r.y & 0xffff)] = e.y;
        g_csr_v[__ldg(g_rowptr_v + v.z) + (r.z & 0xffff)] = e.z;
        g_csr_v[__ldg(g_rowptr_v + v.w) + (r.w & 0xffff)] = e.w;
        g_csr_e[__ldg(g_rowptr_e + e.x) + (r.x >> 16)] = v.x;
        g_csr_e[__ldg(g_rowptr_e + e.y) + (r.y >> 16)] = v.y;
        g_csr_e[__ldg(g_rowptr_e + e.z) + (r.z >> 16)] = v.z;
        g_csr_e[__ldg(g_rowptr_e + e.w) + (r.w >> 16)] = v.w;
    }
}

// ---------------- Agg[e] = sum_{v in e} a_v * X[v];  s_e = sum a_v ------------
// one warp per hyperedge; lane owns 4 cols (fp16 loads, fp32 accumulate)
__global__ __launch_bounds__(256) void k_agg() {
    int w    = (blockIdx.x * blockDim.x + threadIdx.x) >> 5;
    int lane = threadIdx.x & 31;
    if (w >= N_EDGES) return;
    int beg = g_rowptr_e[w];
    int end = g_rowptr_e[w + 1];
    float4 acc = make_float4(0.f, 0.f, 0.f, 0.f);
    float  s   = 0.f;
    int j = beg;
    for (; j + 4 <= end; j += 4) {
        int v0 = __ldg(g_csr_e + j    );
        int v1 = __ldg(g_csr_e + j + 1);
        int v2 = __ldg(g_csr_e + j + 2);
        int v3 = __ldg(g_csr_e + j + 3);
        float a0 = __ldg(g_inv_sqrt_dv + v0);
        float a1 = __ldg(g_inv_sqrt_dv + v1);
        float a2 = __ldg(g_inv_sqrt_dv + v2);
        float a3 = __ldg(g_inv_sqrt_dv + v3);
        uint2 u0 = __ldg((const uint2*)(g_xh + (size_t)v0 * D) + lane);
        uint2 u1 = __ldg((const uint2*)(g_xh + (size_t)v1 * D) + lane);
        uint2 u2 = __ldg((const uint2*)(g_xh + (size_t)v2 * D) + lane);
        uint2 u3 = __ldg((const uint2*)(g_xh + (size_t)v3 * D) + lane);
        float2 f;
        f = __half22float2(*reinterpret_cast<__half2*>(&u0.x)); acc.x += a0*f.x; acc.y += a0*f.y;
        f = __half22float2(*reinterpret_cast<__half2*>(&u0.y)); acc.z += a0*f.x; acc.w += a0*f.y;
        f = __half22float2(*reinterpret_cast<__half2*>(&u1.x)); acc.x += a1*f.x; acc.y += a1*f.y;
        f = __half22float2(*reinterpret_cast<__half2*>(&u1.y)); acc.z += a1*f.x; acc.w += a1*f.y;
        f = __half22float2(*reinterpret_cast<__half2*>(&u2.x)); acc.x += a2*f.x; acc.y += a2*f.y;
        f = __half22float2(*reinterpret_cast<__half2*>(&u2.y)); acc.z += a2*f.x; acc.w += a2*f.y;
        f = __half22float2(*reinterpret_cast<__half2*>(&u3.x)); acc.x += a3*f.x; acc.y += a3*f.y;
        f = __half22float2(*reinterpret_cast<__half2*>(&u3.y)); acc.z += a3*f.x; acc.w += a3*f.y;
        s += a0 + a1 + a2 + a3;
    }
    for (; j < end; j++) {
        int   v = __ldg(g_csr_e + j);
        float a = __ldg(g_inv_sqrt_dv + v);
        uint2 u = __ldg((const uint2*)(g_xh + (size_t)v * D) + lane);
        float2 f;
        f = __half22float2(*reinterpret_cast<__half2*>(&u.x)); acc.x += a*f.x; acc.y += a*f.y;
        f = __half22float2(*reinterpret_cast<__half2*>(&u.y)); acc.z += a*f.x; acc.w += a*f.y;
        s += a;
    }
    ((float4*)(g_agg + (size_t)w * D))[lane] = acc;
    if (lane == 0) g_se[w] = s;
}

// ---------------- Ye = (Agg @ W + s_e * b) * inv_de  (fp16 output) ------------
// one warp per 8 edge-rows: halves W L1 traffic vs 4-row blocking
__global__ __launch_bounds__(256) void k_gemm(const float* __restrict__ Wm, const float* __restrict__ bias) {
    int w    = (blockIdx.x * blockDim.x + threadIdx.x) >> 5;
    int lane = threadIdx.x & 31;
    int r0   = w * 8;
    if (r0 >= N_EDGES) return;

    float4 acc[8];
    #pragma unroll
    for (int r = 0; r < 8; r++) acc[r] = make_float4(0.f, 0.f, 0.f, 0.f);
    const float* A = g_agg + (size_t)r0 * D;

    #pragma unroll 2
    for (int k = 0; k < D; k++) {
        float4 wk = __ldg((const float4*)(Wm + (size_t)k * D) + lane);
        #pragma unroll
        for (int r = 0; r < 8; r++) {
            float a = __ldg(A + (size_t)r * D + k);
            acc[r].x += a * wk.x; acc[r].y += a * wk.y;
            acc[r].z += a * wk.z; acc[r].w += a * wk.w;
        }
    }

    float4 bb = __ldg((const float4*)bias + lane);
    #pragma unroll
    for (int r = 0; r < 8; r++) {
        float se  = g_se[r0 + r];
        float sc  = g_inv_de[r0 + r];
        __half2 h0 = __floats2half2_rn((acc[r].x + se * bb.x) * sc,
                                       (acc[r].y + se * bb.y) * sc);
        __half2 h1 = __floats2half2_rn((acc[r].z + se * bb.z) * sc,
                                       (acc[r].w + se * bb.w) * sc);
        uint2 p = make_uint2(*reinterpret_cast<unsigned*>(&h0),
                             *reinterpret_cast<unsigned*>(&h1));
        ((uint2*)(g_yeh + (size_t)(r0 + r) * D))[lane] = p;
    }
}

// ---------------- out[v] = relu(a_v * sum_{e in v} Ye[e]) ---------------------
__global__ __launch_bounds__(256) void k_gather(float* __restrict__ out) {
    int w    = (blockIdx.x * blockDim.x + threadIdx.x) >> 5;
    int lane = threadIdx.x & 31;
    if (w >= N_NODES) return;
    int beg = g_rowptr_v[w];
    int end = g_rowptr_v[w + 1];
    float4 acc = make_float4(0.f, 0.f, 0.f, 0.f);
    int j = beg;
    for (; j + 4 <= end; j += 4) {
        int e0 = __ldg(g_csr_v + j    );
        int e1 = __ldg(g_csr_v + j + 1);
        int e2 = __ldg(g_csr_v + j + 2);
        int e3 = __ldg(g_csr_v + j + 3);
        uint2 u0 = __ldg((const uint2*)(g_yeh + (size_t)e0 * D) + lane);
        uint2 u1 = __ldg((const uint2*)(g_yeh + (size_t)e1 * D) + lane);
        uint2 u2 = __ldg((const uint2*)(g_yeh + (size_t)e2 * D) + lane);
        uint2 u3 = __ldg((const uint2*)(g_yeh + (size_t)e3 * D) + lane);
        float2 f;
        f = __half22float2(*reinterpret_cast<__half2*>(&u0.x)); acc.x += f.x; acc.y += f.y;
        f = __half22float2(*reinterpret_cast<__half2*>(&u0.y)); acc.z += f.x; acc.w += f.y;
        f = __half22float2(*reinterpret_cast<__half2*>(&u1.x)); acc.x += f.x; acc.y += f.y;
        f = __half22float2(*reinterpret_cast<__half2*>(&u1.y)); acc.z += f.x; acc.w += f.y;
        f = __half22float2(*reinterpret_cast<__half2*>(&u2.x)); acc.x += f.x; acc.y += f.y;
        f = __half22float2(*reinterpret_cast<__half2*>(&u2.y)); acc.z += f.x; acc.w += f.y;
        f = __half22float2(*reinterpret_cast<__half2*>(&u3.x)); acc.x += f.x; acc.y += f.y;
        f = __half22float2(*reinterpret_cast<__half2*>(&u3.y)); acc.z += f.x; acc.w += f.y;
    }
    for (; j < end; j++) {
        int e = __ldg(g_csr_v + j);
        uint2 u = __ldg((const uint2*)(g_yeh + (size_t)e * D) + lane);
        float2 f;
        f = __half22float2(*reinterpret_cast<__half2*>(&u.x)); acc.x += f.x; acc.y += f.y;
        f = __half22float2(*reinterpret_cast<__half2*>(&u.y)); acc.z += f.x; acc.w += f.y;
    }
    float a = g_inv_sqrt_dv[w];
    float4 r;
    r.x = fmaxf(acc.x * a, 0.f);
    r.y = fmaxf(acc.y * a, 0.f);
    r.z = fmaxf(acc.z * a, 0.f);
    r.w = fmaxf(acc.w * a, 0.f);
    ((float4*)(out + (size_t)w * D))[lane] = r;
}

// ---------------- launch -----------------------------------------------------
extern "C" void kernel_launch(void* const* d_in, const int* in_sizes, int n_in,
                              void* d_out, int out_size) {
    const float* X     = (const float*)d_in[0];
    const float* Wm    = (const float*)d_in[1];
    const float* bias  = (const float*)d_in[2];
    const int*   v_idx = (const int*)d_in[3];
    const int*   e_idx = (const int*)d_in[4];
    float*       out   = (float*)d_out;

    void* cnt_ptr = nullptr;
    cudaGetSymbolAddress(&cnt_ptr, g_cnt);
    cudaMemsetAsync(cnt_ptr, 0, NT * sizeof(int));

    k_count  <<<(NNZ_E / 4 + 255) / 256, 256>>>(v_idx, e_idx, X);
    k_scan1  <<<SCAN_NB, 1024>>>();
    k_scan3  <<<(NT + 255) / 256, 256>>>();
    k_scatter<<<(NNZ_E / 4 + 255) / 256, 256>>>(v_idx, e_idx);
    k_agg    <<<(N_EDGES * 32 + 255) / 256, 256>>>();
    k_gemm   <<<((N_EDGES / 8) * 32 + 255) / 256, 256>>>(Wm, bias);
    k_gather <<<(N_NODES * 32 + 255) / 256, 256>>>(out);
}